// round 1
// baseline (speedup 1.0000x reference)
#include <cuda_runtime.h>
#include <cuda_bf16.h>
#include <cstdint>

// Problem constants (fixed by the reference)
constexpr int NN   = 50000;
constexpr int DIN  = 128;
constexpr int DOUT = 128;

// Scratch for the projected features hw = (h @ W) * norm  (25.6 MB)
__device__ float g_hw[(size_t)NN * DOUT];

// ---------------------------------------------------------------------------
// Kernel 1: zero the accumulator (d_out is reused as agg buffer)
// ---------------------------------------------------------------------------
__global__ void zero_kernel(float4* __restrict__ out, int n4) {
    int i = blockIdx.x * blockDim.x + threadIdx.x;
    if (i < n4) out[i] = make_float4(0.f, 0.f, 0.f, 0.f);
}

// ---------------------------------------------------------------------------
// Kernel 2: hw = (h @ W) * norm
// BM=64, BN=128(=DOUT), BK=16, 256 threads, 4x8 register tile per thread.
// ---------------------------------------------------------------------------
__global__ void __launch_bounds__(256) gemm_norm_kernel(
    const float* __restrict__ h,
    const float* __restrict__ W,
    const float* __restrict__ norm)
{
    __shared__ float As[16][64];    // A tile transposed: As[k][m]
    __shared__ float Ws[16][128];   // W tile: Ws[k][n]

    const int tid  = threadIdx.x;
    const int row0 = blockIdx.x * 64;
    const int tx   = tid & 15;      // column group: cols [tx*8, tx*8+8)
    const int ty   = tid >> 4;      // row group:    rows [ty*4, ty*4+4)

    float acc[4][8];
    #pragma unroll
    for (int i = 0; i < 4; i++)
        #pragma unroll
        for (int j = 0; j < 8; j++)
            acc[i][j] = 0.f;

    // A-tile load mapping: each thread loads one float4 per K-step
    const int arow = tid >> 2;          // 0..63
    const int akq  = (tid & 3) * 4;     // 0,4,8,12
    const int grow = row0 + arow;
    const int lrow = (grow < NN) ? grow : 0;   // clamp (store is guarded)

    for (int k0 = 0; k0 < DIN; k0 += 16) {
        // --- load A tile (64x16), transposed into As[k][m] ---
        float4 av = *(const float4*)(h + (size_t)lrow * DIN + k0 + akq);
        As[akq + 0][arow] = av.x;
        As[akq + 1][arow] = av.y;
        As[akq + 2][arow] = av.z;
        As[akq + 3][arow] = av.w;

        // --- load W tile (16x128), coalesced float4 ---
        #pragma unroll
        for (int i = 0; i < 2; i++) {
            int idx = i * 256 + tid;      // 0..511
            int r   = idx >> 5;           // 0..15
            int c   = (idx & 31) * 4;     // 0..124
            *(float4*)&Ws[r][c] = *(const float4*)(W + (size_t)(k0 + r) * DOUT + c);
        }
        __syncthreads();

        #pragma unroll
        for (int k = 0; k < 16; k++) {
            float4 a  = *(const float4*)&As[k][ty * 4];
            float4 b0 = *(const float4*)&Ws[k][tx * 8];
            float4 b1 = *(const float4*)&Ws[k][tx * 8 + 4];
            float avr[4] = {a.x, a.y, a.z, a.w};
            float bvr[8] = {b0.x, b0.y, b0.z, b0.w, b1.x, b1.y, b1.z, b1.w};
            #pragma unroll
            for (int i = 0; i < 4; i++)
                #pragma unroll
                for (int j = 0; j < 8; j++)
                    acc[i][j] = fmaf(avr[i], bvr[j], acc[i][j]);
        }
        __syncthreads();
    }

    // --- epilogue: scale by norm[row], vectorized store ---
    #pragma unroll
    for (int i = 0; i < 4; i++) {
        int r = row0 + ty * 4 + i;
        if (r < NN) {
            float nr = __ldg(norm + r);
            float4 o0 = make_float4(acc[i][0] * nr, acc[i][1] * nr,
                                    acc[i][2] * nr, acc[i][3] * nr);
            float4 o1 = make_float4(acc[i][4] * nr, acc[i][5] * nr,
                                    acc[i][6] * nr, acc[i][7] * nr);
            *(float4*)(g_hw + (size_t)r * DOUT + tx * 8)     = o0;
            *(float4*)(g_hw + (size_t)r * DOUT + tx * 8 + 4) = o1;
        }
    }
}

// ---------------------------------------------------------------------------
// Kernel 3: edge aggregation. One warp per edge: gather hw[src] row (one
// float4 per lane), vector-reduce into out[dst] with red.global.add.v4.f32
// (no return trip, 16B per LTS RMW).
// ---------------------------------------------------------------------------
__global__ void __launch_bounds__(256) agg_kernel(
    const int* __restrict__ src,
    const int* __restrict__ dst,
    float* __restrict__ out,
    int E)
{
    int warp = (blockIdx.x * blockDim.x + threadIdx.x) >> 5;
    int lane = threadIdx.x & 31;
    if (warp >= E) return;

    int s = __ldg(src + warp);
    int d = __ldg(dst + warp);

    float4 v = *(const float4*)(g_hw + (size_t)s * DOUT + lane * 4);
    float* p = out + (size_t)d * DOUT + lane * 4;
    asm volatile("red.global.add.v4.f32 [%0], {%1,%2,%3,%4};"
                 :: "l"(p), "f"(v.x), "f"(v.y), "f"(v.z), "f"(v.w)
                 : "memory");
}

// ---------------------------------------------------------------------------
// Kernel 4: out = relu(out * norm + bias), in place, one float4 per thread.
// ---------------------------------------------------------------------------
__global__ void finalize_kernel(float* __restrict__ out,
                                const float* __restrict__ norm,
                                const float* __restrict__ bias)
{
    int i = blockIdx.x * blockDim.x + threadIdx.x;   // over NN*32 float4s
    if (i >= NN * (DOUT / 4)) return;
    int row = i >> 5;          // DOUT/4 = 32 float4 per row
    int c4  = i & 31;

    float nr = __ldg(norm + row);
    float4 b = *(const float4*)(bias + c4 * 4);
    float4 v = *(float4*)(out + (size_t)i * 4);
    v.x = fmaxf(fmaf(v.x, nr, b.x), 0.f);
    v.y = fmaxf(fmaf(v.y, nr, b.y), 0.f);
    v.z = fmaxf(fmaf(v.z, nr, b.z), 0.f);
    v.w = fmaxf(fmaf(v.w, nr, b.w), 0.f);
    *(float4*)(out + (size_t)i * 4) = v;
}

// ---------------------------------------------------------------------------
// Launch. Input order (metadata): h, weight, bias, norm, src, dst
// ---------------------------------------------------------------------------
extern "C" void kernel_launch(void* const* d_in, const int* in_sizes, int n_in,
                              void* d_out, int out_size)
{
    const float* h    = (const float*)d_in[0];
    const float* W    = (const float*)d_in[1];
    const float* bias = (const float*)d_in[2];
    const float* norm = (const float*)d_in[3];
    const int*   src  = (const int*)d_in[4];
    const int*   dst  = (const int*)d_in[5];
    float*       out  = (float*)d_out;

    const int E  = in_sizes[4];
    const int n4 = NN * (DOUT / 4);            // 1.6M float4s

    // 1) zero accumulator (d_out)
    zero_kernel<<<(n4 + 255) / 256, 256>>>((float4*)out, n4);

    // 2) projection + pre-agg norm scaling into g_hw
    gemm_norm_kernel<<<(NN + 63) / 64, 256>>>(h, W, norm);

    // 3) edge scatter-add (one warp per edge)
    {
        long long total_threads = (long long)E * 32;
        int blocks = (int)((total_threads + 255) / 256);
        agg_kernel<<<blocks, 256>>>(src, dst, out, E);
    }

    // 4) post-agg norm + bias + relu, in place
    finalize_kernel<<<(n4 + 255) / 256, 256>>>(out, norm, bias);
}

// round 2
// speedup vs baseline: 1.3714x; 1.3714x over previous
#include <cuda_runtime.h>
#include <cuda_bf16.h>
#include <cstdint>

// Problem constants (fixed by the reference)
constexpr int NN   = 50000;
constexpr int DIN  = 128;
constexpr int DOUT = 128;
constexpr int ELLW = 64;      // ELL width; Poisson(16) => P(deg>64) ~ 1e-18/node

// Scratch
__device__ float g_hw[(size_t)NN * DOUT];          // (h @ W) * norm   (25.6 MB)
__device__ int   g_ell[(size_t)NN * ELLW];         // per-dst src list (12.8 MB)
__device__ int   g_cnt[NN];                        // per-dst degree

// ---------------------------------------------------------------------------
// Kernel 1: zero the out accumulator (overflow-RED base) + degree counters
// ---------------------------------------------------------------------------
__global__ void zero_kernel(float4* __restrict__ out, int n4) {
    int i = blockIdx.x * blockDim.x + threadIdx.x;
    if (i < n4) out[i] = make_float4(0.f, 0.f, 0.f, 0.f);
    if (i < NN) g_cnt[i] = 0;
}

// ---------------------------------------------------------------------------
// Kernel 2: hw = (h @ W) * norm
// BM=64, BN=128(=DOUT), BK=16, 256 threads, 4x8 register tile per thread.
// ---------------------------------------------------------------------------
__global__ void __launch_bounds__(256) gemm_norm_kernel(
    const float* __restrict__ h,
    const float* __restrict__ W,
    const float* __restrict__ norm)
{
    __shared__ float As[16][64];    // A tile transposed: As[k][m]
    __shared__ float Ws[16][128];   // W tile: Ws[k][n]

    const int tid  = threadIdx.x;
    const int row0 = blockIdx.x * 64;
    const int tx   = tid & 15;      // column group: cols [tx*8, tx*8+8)
    const int ty   = tid >> 4;      // row group:    rows [ty*4, ty*4+4)

    float acc[4][8];
    #pragma unroll
    for (int i = 0; i < 4; i++)
        #pragma unroll
        for (int j = 0; j < 8; j++)
            acc[i][j] = 0.f;

    const int arow = tid >> 2;          // 0..63
    const int akq  = (tid & 3) * 4;     // 0,4,8,12
    const int grow = row0 + arow;
    const int lrow = (grow < NN) ? grow : 0;   // clamp (store is guarded)

    for (int k0 = 0; k0 < DIN; k0 += 16) {
        float4 av = *(const float4*)(h + (size_t)lrow * DIN + k0 + akq);
        As[akq + 0][arow] = av.x;
        As[akq + 1][arow] = av.y;
        As[akq + 2][arow] = av.z;
        As[akq + 3][arow] = av.w;

        #pragma unroll
        for (int i = 0; i < 2; i++) {
            int idx = i * 256 + tid;
            int r   = idx >> 5;
            int c   = (idx & 31) * 4;
            *(float4*)&Ws[r][c] = *(const float4*)(W + (size_t)(k0 + r) * DOUT + c);
        }
        __syncthreads();

        #pragma unroll
        for (int k = 0; k < 16; k++) {
            float4 a  = *(const float4*)&As[k][ty * 4];
            float4 b0 = *(const float4*)&Ws[k][tx * 8];
            float4 b1 = *(const float4*)&Ws[k][tx * 8 + 4];
            float avr[4] = {a.x, a.y, a.z, a.w};
            float bvr[8] = {b0.x, b0.y, b0.z, b0.w, b1.x, b1.y, b1.z, b1.w};
            #pragma unroll
            for (int i = 0; i < 4; i++)
                #pragma unroll
                for (int j = 0; j < 8; j++)
                    acc[i][j] = fmaf(avr[i], bvr[j], acc[i][j]);
        }
        __syncthreads();
    }

    #pragma unroll
    for (int i = 0; i < 4; i++) {
        int r = row0 + ty * 4 + i;
        if (r < NN) {
            float nr = __ldg(norm + r);
            float4 o0 = make_float4(acc[i][0] * nr, acc[i][1] * nr,
                                    acc[i][2] * nr, acc[i][3] * nr);
            float4 o1 = make_float4(acc[i][4] * nr, acc[i][5] * nr,
                                    acc[i][6] * nr, acc[i][7] * nr);
            *(float4*)(g_hw + (size_t)r * DOUT + tx * 8)     = o0;
            *(float4*)(g_hw + (size_t)r * DOUT + tx * 8 + 4) = o1;
        }
    }
}

// ---------------------------------------------------------------------------
// Kernel 3: build ELL adjacency. One thread per edge.
// Overflow (deg > ELLW, ~impossible) falls back to fp RED into out[dst].
// ---------------------------------------------------------------------------
__global__ void __launch_bounds__(256) build_kernel(
    const int* __restrict__ src,
    const int* __restrict__ dst,
    float* __restrict__ out,
    int E)
{
    int e = blockIdx.x * blockDim.x + threadIdx.x;
    if (e >= E) return;
    int s = __ldg(src + e);
    int d = __ldg(dst + e);
    int pos = atomicAdd(&g_cnt[d], 1);
    if (pos < ELLW) {
        g_ell[(size_t)d * ELLW + pos] = s;
    } else {
        // exactness fallback: RED the whole row (runs ~never)
        const float* hs = g_hw + (size_t)s * DOUT;
        float* po = out + (size_t)d * DOUT;
        #pragma unroll 4
        for (int j = 0; j < DOUT; j += 4) {
            float4 v = *(const float4*)(hs + j);
            asm volatile("red.global.add.v4.f32 [%0], {%1,%2,%3,%4};"
                         :: "l"(po + j), "f"(v.x), "f"(v.y), "f"(v.z), "f"(v.w)
                         : "memory");
        }
    }
}

// ---------------------------------------------------------------------------
// Kernel 4: aggregate + epilogue. One warp per dst node.
// Prefetch up to 64 src ids (2 coalesced loads + shfl), register-accumulate
// gathered rows, then out = relu(acc*norm + bias).
// ---------------------------------------------------------------------------
__global__ void __launch_bounds__(256) agg_kernel(
    float* __restrict__ out,
    const float* __restrict__ norm,
    const float* __restrict__ bias)
{
    int warp = (blockIdx.x * blockDim.x + threadIdx.x) >> 5;
    int lane = threadIdx.x & 31;
    if (warp >= NN) return;
    const int d = warp;

    int cnt_raw = __ldg(&g_cnt[d]);
    int n = cnt_raw < ELLW ? cnt_raw : ELLW;

    // prefetch src ids: lane i holds slots i and 32+i
    const int* lst = g_ell + (size_t)d * ELLW;
    int id0 = lst[lane];
    int id1 = lst[32 + lane];

    float4 acc = make_float4(0.f, 0.f, 0.f, 0.f);
    const int co = lane * 4;   // this lane's 4 columns

    int i = 0;
    // unrolled by 2 for MLP
    for (; i + 2 <= n; i += 2) {
        int sa = __shfl_sync(0xffffffffu, (i & 32) ? id1 : id0, i & 31);
        int sb = __shfl_sync(0xffffffffu, ((i + 1) & 32) ? id1 : id0, (i + 1) & 31);
        float4 va = *(const float4*)(g_hw + (size_t)sa * DOUT + co);
        float4 vb = *(const float4*)(g_hw + (size_t)sb * DOUT + co);
        acc.x += va.x + vb.x;
        acc.y += va.y + vb.y;
        acc.z += va.z + vb.z;
        acc.w += va.w + vb.w;
    }
    if (i < n) {
        int sa = __shfl_sync(0xffffffffu, (i & 32) ? id1 : id0, i & 31);
        float4 va = *(const float4*)(g_hw + (size_t)sa * DOUT + co);
        acc.x += va.x; acc.y += va.y; acc.z += va.z; acc.w += va.w;
    }

    // overflow contributions already RED'd into out (zeroed base)
    if (cnt_raw > ELLW) {
        float4 ov = *(const float4*)(out + (size_t)d * DOUT + co);
        acc.x += ov.x; acc.y += ov.y; acc.z += ov.z; acc.w += ov.w;
    }

    float nr = __ldg(norm + d);
    float4 b = *(const float4*)(bias + co);
    float4 r;
    r.x = fmaxf(fmaf(acc.x, nr, b.x), 0.f);
    r.y = fmaxf(fmaf(acc.y, nr, b.y), 0.f);
    r.z = fmaxf(fmaf(acc.z, nr, b.z), 0.f);
    r.w = fmaxf(fmaf(acc.w, nr, b.w), 0.f);
    *(float4*)(out + (size_t)d * DOUT + co) = r;
}

// ---------------------------------------------------------------------------
// Launch. Input order (metadata): h, weight, bias, norm, src, dst
// ---------------------------------------------------------------------------
extern "C" void kernel_launch(void* const* d_in, const int* in_sizes, int n_in,
                              void* d_out, int out_size)
{
    const float* h    = (const float*)d_in[0];
    const float* W    = (const float*)d_in[1];
    const float* bias = (const float*)d_in[2];
    const float* norm = (const float*)d_in[3];
    const int*   src  = (const int*)d_in[4];
    const int*   dst  = (const int*)d_in[5];
    float*       out  = (float*)d_out;

    const int E  = in_sizes[4];
    const int n4 = NN * (DOUT / 4);            // 1.6M float4s

    // 1) zero accumulator + degree counters
    zero_kernel<<<(n4 + 255) / 256, 256>>>((float4*)out, n4);

    // 2) projection + pre-agg norm scaling into g_hw
    gemm_norm_kernel<<<(NN + 63) / 64, 256>>>(h, W, norm);

    // 3) build per-dst adjacency (ELL)
    build_kernel<<<(E + 255) / 256, 256>>>(src, dst, out, E);

    // 4) gather-aggregate + fused norm/bias/relu (one warp per node)
    {
        int warps_needed = NN;
        int blocks = (warps_needed * 32 + 255) / 256;
        agg_kernel<<<blocks, 256>>>(out, norm, bias);
    }
}

// round 4
// speedup vs baseline: 1.8260x; 1.3315x over previous
#include <cuda_runtime.h>
#include <cuda_bf16.h>
#include <cstdint>

// Problem constants
constexpr int NN   = 50000;
constexpr int DIN  = 128;
constexpr int DOUT = 128;
constexpr int ELLW = 64;

// Scratch
__device__ float g_hw[(size_t)NN * DOUT];
__device__ int   g_ell[(size_t)NN * ELLW];
__device__ int   g_cnt[NN];

__device__ __forceinline__ float to_tf32(float x) {
    float r;
    asm("cvt.rna.tf32.f32 %0, %1;" : "=f"(r) : "f"(x));
    return r;
}

// m16n8k8 tf32 mma: D += A*B (C=D accumulate in place)
#define MMA_TF32(d, a, b)                                                     \
    asm volatile("mma.sync.aligned.m16n8k8.row.col.f32.tf32.tf32.f32 "        \
        "{%0,%1,%2,%3}, {%4,%5,%6,%7}, {%8,%9}, {%0,%1,%2,%3};"               \
        : "+f"((d)[0]), "+f"((d)[1]), "+f"((d)[2]), "+f"((d)[3])              \
        : "r"(__float_as_uint((a)[0])), "r"(__float_as_uint((a)[1])),         \
          "r"(__float_as_uint((a)[2])), "r"(__float_as_uint((a)[3])),         \
          "r"(__float_as_uint((b)[0])), "r"(__float_as_uint((b)[1])))

// Smem strides (floats); both divisible by 4 (16B-aligned rows) and
// chosen for conflict-free fragment reads.
constexpr int AST = 68;    // A tile stride  (bank = (4g+t)%32, all distinct)
constexpr int WST = 136;   // W tile stride  (bank = (8t+g)%32, all distinct)
constexpr int SMEM_FLOATS = 2 * (128 * AST) + 2 * (64 * WST);
constexpr int SMEM_BYTES  = SMEM_FLOATS * 4;   // 139,264 B

// ---------------------------------------------------------------------------
// Kernel 1: zero degree counters only (out is fully overwritten by agg)
// ---------------------------------------------------------------------------
__global__ void zero_cnt_kernel() {
    int i = blockIdx.x * blockDim.x + threadIdx.x;
    if (i < NN) g_cnt[i] = 0;
}

// ---------------------------------------------------------------------------
// Kernel 2: hw = (h @ W) * norm  via mma.sync tf32 (3xTF32 decomposition).
// CTA: 128 rows x 128 cols, 8 warps, warp tile 32x64 (2x8 m16n8k8 frags).
// K = 128 in two 64-chunks.
// ---------------------------------------------------------------------------
__global__ void __launch_bounds__(256, 1) gemm_mma_kernel(
    const float* __restrict__ h,
    const float* __restrict__ W,
    const float* __restrict__ norm)
{
    extern __shared__ float smem[];
    float* As_h = smem;                       // [128][AST]
    float* As_l = As_h + 128 * AST;
    float* Ws_h = As_l + 128 * AST;           // [64][WST]
    float* Ws_l = Ws_h + 64 * WST;

    const int tid  = threadIdx.x;
    const int lane = tid & 31;
    const int wid  = tid >> 5;
    const int wm   = wid & 3;                 // m block (32 rows)
    const int wn   = wid >> 2;                // n block (64 cols)
    const int g    = lane >> 2;               // lane/4
    const int t    = lane & 3;                // lane%4
    const int row0 = blockIdx.x * 128;

    float acc[2][8][4];
    #pragma unroll
    for (int mt = 0; mt < 2; mt++)
        #pragma unroll
        for (int nt = 0; nt < 8; nt++)
            #pragma unroll
            for (int e = 0; e < 4; e++)
                acc[mt][nt][e] = 0.f;

    for (int c = 0; c < 2; c++) {
        const int k0 = c * 64;

        // ---- fill W chunk (64 k x 128 n), hi/lo ----
        for (int idx = tid; idx < 64 * 32; idx += 256) {
            int k  = idx >> 5;                 // 0..63
            int n4 = (idx & 31) << 2;          // 0..124
            float4 w = *(const float4*)(W + (size_t)(k0 + k) * DOUT + n4);
            float v[4] = {w.x, w.y, w.z, w.w};
            float4 hv, lv;
            float* hp = &hv.x; float* lp = &lv.x;
            #pragma unroll
            for (int e = 0; e < 4; e++) {
                float hi = to_tf32(v[e]);
                hp[e] = hi;
                lp[e] = to_tf32(v[e] - hi);
            }
            *(float4*)(Ws_h + k * WST + n4) = hv;
            *(float4*)(Ws_l + k * WST + n4) = lv;
        }

        // ---- fill A chunk (128 rows x 64 k), hi/lo ----
        for (int idx = tid; idx < 128 * 16; idx += 256) {
            int r  = idx >> 4;                 // 0..127
            int k4 = (idx & 15) << 2;          // 0..60
            int gr = row0 + r;
            if (gr >= NN) gr = NN - 1;         // clamp (stores guarded later)
            float4 v = *(const float4*)(h + (size_t)gr * DIN + k0 + k4);
            float vv[4] = {v.x, v.y, v.z, v.w};
            float4 hv, lv;
            float* hp = &hv.x; float* lp = &lv.x;
            #pragma unroll
            for (int e = 0; e < 4; e++) {
                float hi = to_tf32(vv[e]);
                hp[e] = hi;
                lp[e] = to_tf32(vv[e] - hi);
            }
            *(float4*)(As_h + r * AST + k4) = hv;
            *(float4*)(As_l + r * AST + k4) = lv;
        }
        __syncthreads();

        // ---- 8 k-steps of 8 ----
        #pragma unroll 4
        for (int ks = 0; ks < 8; ks++) {
            const int kk = ks * 8;

            float ah[2][4], al[2][4];
            #pragma unroll
            for (int mt = 0; mt < 2; mt++) {
                int r = wm * 32 + mt * 16 + g;
                ah[mt][0] = As_h[r * AST + kk + t];
                ah[mt][1] = As_h[(r + 8) * AST + kk + t];
                ah[mt][2] = As_h[r * AST + kk + 4 + t];
                ah[mt][3] = As_h[(r + 8) * AST + kk + 4 + t];
                al[mt][0] = As_l[r * AST + kk + t];
                al[mt][1] = As_l[(r + 8) * AST + kk + t];
                al[mt][2] = As_l[r * AST + kk + 4 + t];
                al[mt][3] = As_l[(r + 8) * AST + kk + 4 + t];
            }

            float bh[8][2], bl[8][2];
            #pragma unroll
            for (int nt = 0; nt < 8; nt++) {
                int n = wn * 64 + nt * 8 + g;
                bh[nt][0] = Ws_h[(kk + t) * WST + n];
                bh[nt][1] = Ws_h[(kk + 4 + t) * WST + n];
                bl[nt][0] = Ws_l[(kk + t) * WST + n];
                bl[nt][1] = Ws_l[(kk + 4 + t) * WST + n];
            }

            #pragma unroll
            for (int mt = 0; mt < 2; mt++)
                #pragma unroll
                for (int nt = 0; nt < 8; nt++) {
                    MMA_TF32(acc[mt][nt], ah[mt], bh[nt]);
                    MMA_TF32(acc[mt][nt], al[mt], bh[nt]);
                    MMA_TF32(acc[mt][nt], ah[mt], bl[nt]);
                }
        }
        __syncthreads();
    }

    // ---- epilogue: scale by norm[row], store g_hw ----
    // C frag: c0,c1 -> (row g, cols 2t,2t+1); c2,c3 -> (row g+8, same cols)
    #pragma unroll
    for (int mt = 0; mt < 2; mt++) {
        int r_lo = row0 + wm * 32 + mt * 16 + g;
        int r_hi = r_lo + 8;
        float n_lo = (r_lo < NN) ? __ldg(norm + r_lo) : 0.f;
        float n_hi = (r_hi < NN) ? __ldg(norm + r_hi) : 0.f;
        #pragma unroll
        for (int nt = 0; nt < 8; nt++) {
            int col = wn * 64 + nt * 8 + 2 * t;
            if (r_lo < NN) {
                float2 o = make_float2(acc[mt][nt][0] * n_lo, acc[mt][nt][1] * n_lo);
                *(float2*)(g_hw + (size_t)r_lo * DOUT + col) = o;
            }
            if (r_hi < NN) {
                float2 o = make_float2(acc[mt][nt][2] * n_hi, acc[mt][nt][3] * n_hi);
                *(float2*)(g_hw + (size_t)r_hi * DOUT + col) = o;
            }
        }
    }
}

// ---------------------------------------------------------------------------
// Kernel 3: build ELL adjacency. One thread per edge.
// ---------------------------------------------------------------------------
__global__ void __launch_bounds__(256) build_kernel(
    const int* __restrict__ src,
    const int* __restrict__ dst,
    float* __restrict__ out,
    int E)
{
    int e = blockIdx.x * blockDim.x + threadIdx.x;
    if (e >= E) return;
    int s = __ldg(src + e);
    int d = __ldg(dst + e);
    int pos = atomicAdd(&g_cnt[d], 1);
    if (pos < ELLW) {
        g_ell[(size_t)d * ELLW + pos] = s;
    } else {
        // overflow fallback (statistically never with Poisson(16) degrees)
        const float* hs = g_hw + (size_t)s * DOUT;
        float* po = out + (size_t)d * DOUT;
        #pragma unroll 4
        for (int j = 0; j < DOUT; j += 4) {
            float4 v = *(const float4*)(hs + j);
            asm volatile("red.global.add.v4.f32 [%0], {%1,%2,%3,%4};"
                         :: "l"(po + j), "f"(v.x), "f"(v.y), "f"(v.z), "f"(v.w)
                         : "memory");
        }
    }
}

// ---------------------------------------------------------------------------
// Kernel 4: aggregate + fused epilogue. One warp per dst node.
// ---------------------------------------------------------------------------
__global__ void __launch_bounds__(256) agg_kernel(
    float* __restrict__ out,
    const float* __restrict__ norm,
    const float* __restrict__ bias)
{
    int warp = (blockIdx.x * blockDim.x + threadIdx.x) >> 5;
    int lane = threadIdx.x & 31;
    if (warp >= NN) return;
    const int d = warp;

    int cnt_raw = __ldg(&g_cnt[d]);
    int n = cnt_raw < ELLW ? cnt_raw : ELLW;

    const int* lst = g_ell + (size_t)d * ELLW;
    int id0 = lst[lane];
    int id1 = lst[32 + lane];

    float4 acc = make_float4(0.f, 0.f, 0.f, 0.f);
    const int co = lane * 4;

    int i = 0;
    for (; i + 2 <= n; i += 2) {
        int sa = __shfl_sync(0xffffffffu, (i & 32) ? id1 : id0, i & 31);
        int sb = __shfl_sync(0xffffffffu, ((i + 1) & 32) ? id1 : id0, (i + 1) & 31);
        float4 va = *(const float4*)(g_hw + (size_t)sa * DOUT + co);
        float4 vb = *(const float4*)(g_hw + (size_t)sb * DOUT + co);
        acc.x += va.x + vb.x;
        acc.y += va.y + vb.y;
        acc.z += va.z + vb.z;
        acc.w += va.w + vb.w;
    }
    if (i < n) {
        int sa = __shfl_sync(0xffffffffu, (i & 32) ? id1 : id0, i & 31);
        float4 va = *(const float4*)(g_hw + (size_t)sa * DOUT + co);
        acc.x += va.x; acc.y += va.y; acc.z += va.z; acc.w += va.w;
    }

    if (cnt_raw > ELLW) {   // never in practice
        float4 ov = *(const float4*)(out + (size_t)d * DOUT + co);
        acc.x += ov.x; acc.y += ov.y; acc.z += ov.z; acc.w += ov.w;
    }

    float nr = __ldg(norm + d);
    float4 b = *(const float4*)(bias + co);
    float4 r;
    r.x = fmaxf(fmaf(acc.x, nr, b.x), 0.f);
    r.y = fmaxf(fmaf(acc.y, nr, b.y), 0.f);
    r.z = fmaxf(fmaf(acc.z, nr, b.z), 0.f);
    r.w = fmaxf(fmaf(acc.w, nr, b.w), 0.f);
    *(float4*)(out + (size_t)d * DOUT + co) = r;
}

// ---------------------------------------------------------------------------
// Launch. Input order (metadata): h, weight, bias, norm, src, dst
// ---------------------------------------------------------------------------
extern "C" void kernel_launch(void* const* d_in, const int* in_sizes, int n_in,
                              void* d_out, int out_size)
{
    const float* h    = (const float*)d_in[0];
    const float* W    = (const float*)d_in[1];
    const float* bias = (const float*)d_in[2];
    const float* norm = (const float*)d_in[3];
    const int*   src  = (const int*)d_in[4];
    const int*   dst  = (const int*)d_in[5];
    float*       out  = (float*)d_out;

    const int E = in_sizes[4];

    static bool attr_set = false;
    if (!attr_set) {
        cudaFuncSetAttribute(gemm_mma_kernel,
                             cudaFuncAttributeMaxDynamicSharedMemorySize, SMEM_BYTES);
        attr_set = true;
    }

    // 1) zero degree counters
    zero_cnt_kernel<<<(NN + 255) / 256, 256>>>();

    // 2) projection + pre-agg norm scaling into g_hw (tf32 tensor cores)
    gemm_mma_kernel<<<(NN + 127) / 128, 256, SMEM_BYTES>>>(h, W, norm);

    // 3) build per-dst adjacency (ELL)
    build_kernel<<<(E + 255) / 256, 256>>>(src, dst, out, E);

    // 4) gather-aggregate + fused norm/bias/relu (one warp per node)
    agg_kernel<<<(NN * 32 + 255) / 256, 256>>>(out, norm, bias);
}

// round 5
// speedup vs baseline: 2.0932x; 1.1463x over previous
#include <cuda_runtime.h>
#include <cuda_fp16.h>
#include <cstdint>

// Problem constants
constexpr int NN   = 50000;
constexpr int DIN  = 128;
constexpr int DOUT = 128;
constexpr int ELLW = 64;

// Scratch
__device__ __half   g_hw[(size_t)NN * DOUT];        // fp16 projected features (12.8 MB)
__device__ uint16_t g_ell[(size_t)NN * ELLW];       // packed src ids (6.4 MB)
__device__ int      g_cnt[NN];

__device__ __forceinline__ float to_tf32(float x) {
    float r;
    asm("cvt.rna.tf32.f32 %0, %1;" : "=f"(r) : "f"(x));
    return r;
}

// m16n8k8 tf32 mma: D += A*B
#define MMA_TF32(d, a, b)                                                     \
    asm volatile("mma.sync.aligned.m16n8k8.row.col.f32.tf32.tf32.f32 "        \
        "{%0,%1,%2,%3}, {%4,%5,%6,%7}, {%8,%9}, {%0,%1,%2,%3};"               \
        : "+f"((d)[0]), "+f"((d)[1]), "+f"((d)[2]), "+f"((d)[3])              \
        : "r"(__float_as_uint((a)[0])), "r"(__float_as_uint((a)[1])),         \
          "r"(__float_as_uint((a)[2])), "r"(__float_as_uint((a)[3])),         \
          "r"(__float_as_uint((b)[0])), "r"(__float_as_uint((b)[1])))

constexpr int AST = 68;    // A tile stride (floats)
constexpr int WST = 136;   // W tile stride (floats)
constexpr int SMEM_FLOATS = 2 * (128 * AST) + 2 * (64 * WST);
constexpr int SMEM_BYTES  = SMEM_FLOATS * 4;   // 139,264 B

// ---------------------------------------------------------------------------
// Kernel 1: hw = fp16((h @ W) * norm) via mma.sync tf32 (3xTF32).
// Also zeroes g_cnt (grid covers NN; build runs in a later kernel).
// CTA: 128 rows x 128 cols, 8 warps, warp tile 32x64. K = 128 in two 64-chunks.
// ---------------------------------------------------------------------------
__global__ void __launch_bounds__(256, 1) gemm_mma_kernel(
    const float* __restrict__ h,
    const float* __restrict__ W,
    const float* __restrict__ norm)
{
    // fold in counter zeroing (no sync needed; consumed by a later kernel)
    {
        int gi = blockIdx.x * blockDim.x + threadIdx.x;
        if (gi < NN) g_cnt[gi] = 0;
    }

    extern __shared__ float smem[];
    float* As_h = smem;                       // [128][AST]
    float* As_l = As_h + 128 * AST;
    float* Ws_h = As_l + 128 * AST;           // [64][WST]
    float* Ws_l = Ws_h + 64 * WST;

    const int tid  = threadIdx.x;
    const int lane = tid & 31;
    const int wid  = tid >> 5;
    const int wm   = wid & 3;                 // m block (32 rows)
    const int wn   = wid >> 2;                // n block (64 cols)
    const int g    = lane >> 2;
    const int t    = lane & 3;
    const int row0 = blockIdx.x * 128;

    float acc[2][8][4];
    #pragma unroll
    for (int mt = 0; mt < 2; mt++)
        #pragma unroll
        for (int nt = 0; nt < 8; nt++)
            #pragma unroll
            for (int e = 0; e < 4; e++)
                acc[mt][nt][e] = 0.f;

    for (int c = 0; c < 2; c++) {
        const int k0 = c * 64;

        for (int idx = tid; idx < 64 * 32; idx += 256) {
            int k  = idx >> 5;
            int n4 = (idx & 31) << 2;
            float4 w = *(const float4*)(W + (size_t)(k0 + k) * DOUT + n4);
            float v[4] = {w.x, w.y, w.z, w.w};
            float4 hv, lv;
            float* hp = &hv.x; float* lp = &lv.x;
            #pragma unroll
            for (int e = 0; e < 4; e++) {
                float hi = to_tf32(v[e]);
                hp[e] = hi;
                lp[e] = to_tf32(v[e] - hi);
            }
            *(float4*)(Ws_h + k * WST + n4) = hv;
            *(float4*)(Ws_l + k * WST + n4) = lv;
        }

        for (int idx = tid; idx < 128 * 16; idx += 256) {
            int r  = idx >> 4;
            int k4 = (idx & 15) << 2;
            int gr = row0 + r;
            if (gr >= NN) gr = NN - 1;
            float4 v = *(const float4*)(h + (size_t)gr * DIN + k0 + k4);
            float vv[4] = {v.x, v.y, v.z, v.w};
            float4 hv, lv;
            float* hp = &hv.x; float* lp = &lv.x;
            #pragma unroll
            for (int e = 0; e < 4; e++) {
                float hi = to_tf32(vv[e]);
                hp[e] = hi;
                lp[e] = to_tf32(vv[e] - hi);
            }
            *(float4*)(As_h + r * AST + k4) = hv;
            *(float4*)(As_l + r * AST + k4) = lv;
        }
        __syncthreads();

        #pragma unroll 4
        for (int ks = 0; ks < 8; ks++) {
            const int kk = ks * 8;

            float ah[2][4], al[2][4];
            #pragma unroll
            for (int mt = 0; mt < 2; mt++) {
                int r = wm * 32 + mt * 16 + g;
                ah[mt][0] = As_h[r * AST + kk + t];
                ah[mt][1] = As_h[(r + 8) * AST + kk + t];
                ah[mt][2] = As_h[r * AST + kk + 4 + t];
                ah[mt][3] = As_h[(r + 8) * AST + kk + 4 + t];
                al[mt][0] = As_l[r * AST + kk + t];
                al[mt][1] = As_l[(r + 8) * AST + kk + t];
                al[mt][2] = As_l[r * AST + kk + 4 + t];
                al[mt][3] = As_l[(r + 8) * AST + kk + 4 + t];
            }

            float bh[8][2], bl[8][2];
            #pragma unroll
            for (int nt = 0; nt < 8; nt++) {
                int n = wn * 64 + nt * 8 + g;
                bh[nt][0] = Ws_h[(kk + t) * WST + n];
                bh[nt][1] = Ws_h[(kk + 4 + t) * WST + n];
                bl[nt][0] = Ws_l[(kk + t) * WST + n];
                bl[nt][1] = Ws_l[(kk + 4 + t) * WST + n];
            }

            #pragma unroll
            for (int mt = 0; mt < 2; mt++)
                #pragma unroll
                for (int nt = 0; nt < 8; nt++) {
                    MMA_TF32(acc[mt][nt], ah[mt], bh[nt]);
                    MMA_TF32(acc[mt][nt], al[mt], bh[nt]);
                    MMA_TF32(acc[mt][nt], ah[mt], bl[nt]);
                }
        }
        __syncthreads();
    }

    // ---- epilogue: scale by norm[row], convert to fp16, store g_hw ----
    #pragma unroll
    for (int mt = 0; mt < 2; mt++) {
        int r_lo = row0 + wm * 32 + mt * 16 + g;
        int r_hi = r_lo + 8;
        float n_lo = (r_lo < NN) ? __ldg(norm + r_lo) : 0.f;
        float n_hi = (r_hi < NN) ? __ldg(norm + r_hi) : 0.f;
        #pragma unroll
        for (int nt = 0; nt < 8; nt++) {
            int col = wn * 64 + nt * 8 + 2 * t;
            if (r_lo < NN) {
                __half2 o = __floats2half2_rn(acc[mt][nt][0] * n_lo,
                                              acc[mt][nt][1] * n_lo);
                *(__half2*)(g_hw + (size_t)r_lo * DOUT + col) = o;
            }
            if (r_hi < NN) {
                __half2 o = __floats2half2_rn(acc[mt][nt][2] * n_hi,
                                              acc[mt][nt][3] * n_hi);
                *(__half2*)(g_hw + (size_t)r_hi * DOUT + col) = o;
            }
        }
    }
}

// ---------------------------------------------------------------------------
// Kernel 2: build ELL adjacency (u16 ids). One thread per edge.
// ---------------------------------------------------------------------------
__global__ void __launch_bounds__(256) build_kernel(
    const int* __restrict__ src,
    const int* __restrict__ dst,
    float* __restrict__ out,
    int E)
{
    int e = blockIdx.x * blockDim.x + threadIdx.x;
    if (e >= E) return;
    int s = __ldg(src + e);
    int d = __ldg(dst + e);
    int pos = atomicAdd(&g_cnt[d], 1);
    if (pos < ELLW) {
        g_ell[(size_t)d * ELLW + pos] = (uint16_t)s;
    } else {
        // overflow fallback (statistically never; degrees ~ Poisson(16))
        const __half* hs = g_hw + (size_t)s * DOUT;
        float* po = out + (size_t)d * DOUT;
        for (int j = 0; j < DOUT; j += 2) {
            float2 v = __half22float2(*(const __half2*)(hs + j));
            asm volatile("red.global.add.f32 [%0], %1;" :: "l"(po + j),     "f"(v.x) : "memory");
            asm volatile("red.global.add.f32 [%0], %1;" :: "l"(po + j + 1), "f"(v.y) : "memory");
        }
    }
}

// ---------------------------------------------------------------------------
// Kernel 3: aggregate + fused epilogue. One warp per dst node.
// Each lane owns 4 columns (8 bytes fp16). Ids packed 2-per-register.
// ---------------------------------------------------------------------------
__global__ void __launch_bounds__(256) agg_kernel(
    float* __restrict__ out,
    const float* __restrict__ norm,
    const float* __restrict__ bias)
{
    int warp = (blockIdx.x * blockDim.x + threadIdx.x) >> 5;
    int lane = threadIdx.x & 31;
    if (warp >= NN) return;
    const int d = warp;

    int cnt_raw = __ldg(&g_cnt[d]);
    int n = cnt_raw < ELLW ? cnt_raw : ELLW;

    // lane i holds packed ids for slots 2i, 2i+1 (covers all 64)
    uint32_t packed = *(const uint32_t*)(g_ell + (size_t)d * ELLW + 2 * lane);

    float4 acc = make_float4(0.f, 0.f, 0.f, 0.f);
    const int co = lane * 4;   // 4 fp16 columns per lane

    #define GET_ID(j) ({                                                   \
        uint32_t _p = __shfl_sync(0xffffffffu, packed, (j) >> 1);          \
        (int)(((j) & 1) ? (_p >> 16) : (_p & 0xffffu)); })

    #define ACC_ROW(sid) do {                                              \
        uint2 _u = *(const uint2*)(g_hw + (size_t)(sid) * DOUT + co);      \
        float2 _a = __half22float2(*(__half2*)&_u.x);                      \
        float2 _b = __half22float2(*(__half2*)&_u.y);                      \
        acc.x += _a.x; acc.y += _a.y; acc.z += _b.x; acc.w += _b.y; } while (0)

    int i = 0;
    for (; i + 4 <= n; i += 4) {
        int s0 = GET_ID(i);
        int s1 = GET_ID(i + 1);
        int s2 = GET_ID(i + 2);
        int s3 = GET_ID(i + 3);
        uint2 u0 = *(const uint2*)(g_hw + (size_t)s0 * DOUT + co);
        uint2 u1 = *(const uint2*)(g_hw + (size_t)s1 * DOUT + co);
        uint2 u2 = *(const uint2*)(g_hw + (size_t)s2 * DOUT + co);
        uint2 u3 = *(const uint2*)(g_hw + (size_t)s3 * DOUT + co);
        float2 a0 = __half22float2(*(__half2*)&u0.x), b0 = __half22float2(*(__half2*)&u0.y);
        float2 a1 = __half22float2(*(__half2*)&u1.x), b1 = __half22float2(*(__half2*)&u1.y);
        float2 a2 = __half22float2(*(__half2*)&u2.x), b2 = __half22float2(*(__half2*)&u2.y);
        float2 a3 = __half22float2(*(__half2*)&u3.x), b3 = __half22float2(*(__half2*)&u3.y);
        acc.x += (a0.x + a1.x) + (a2.x + a3.x);
        acc.y += (a0.y + a1.y) + (a2.y + a3.y);
        acc.z += (b0.x + b1.x) + (b2.x + b3.x);
        acc.w += (b0.y + b1.y) + (b2.y + b3.y);
    }
    for (; i < n; i++) {
        int s0 = GET_ID(i);
        ACC_ROW(s0);
    }

    if (cnt_raw > ELLW) {   // never in practice
        float4 ov = *(const float4*)(out + (size_t)d * DOUT + co);
        acc.x += ov.x; acc.y += ov.y; acc.z += ov.z; acc.w += ov.w;
    }

    float nr = __ldg(norm + d);
    float4 b = *(const float4*)(bias + co);
    float4 r;
    r.x = fmaxf(fmaf(acc.x, nr, b.x), 0.f);
    r.y = fmaxf(fmaf(acc.y, nr, b.y), 0.f);
    r.z = fmaxf(fmaf(acc.z, nr, b.z), 0.f);
    r.w = fmaxf(fmaf(acc.w, nr, b.w), 0.f);
    *(float4*)(out + (size_t)d * DOUT + co) = r;

    #undef GET_ID
    #undef ACC_ROW
}

// ---------------------------------------------------------------------------
// Launch. Input order (metadata): h, weight, bias, norm, src, dst
// ---------------------------------------------------------------------------
extern "C" void kernel_launch(void* const* d_in, const int* in_sizes, int n_in,
                              void* d_out, int out_size)
{
    const float* h    = (const float*)d_in[0];
    const float* W    = (const float*)d_in[1];
    const float* bias = (const float*)d_in[2];
    const float* norm = (const float*)d_in[3];
    const int*   src  = (const int*)d_in[4];
    const int*   dst  = (const int*)d_in[5];
    float*       out  = (float*)d_out;

    const int E = in_sizes[4];

    cudaFuncSetAttribute(gemm_mma_kernel,
                         cudaFuncAttributeMaxDynamicSharedMemorySize, SMEM_BYTES);

    // 1) projection (+ counter zeroing) -> fp16 g_hw
    gemm_mma_kernel<<<(NN + 127) / 128, 256, SMEM_BYTES>>>(h, W, norm);

    // 2) build per-dst adjacency (ELL, u16)
    build_kernel<<<(E + 255) / 256, 256>>>(src, dst, out, E);

    // 3) gather-aggregate + fused norm/bias/relu (one warp per node)
    agg_kernel<<<(NN * 32 + 255) / 256, 256>>>(out, norm, bias);
}